// round 17
// baseline (speedup 1.0000x reference)
#include <cuda_runtime.h>
#include <cstdint>

// Shapes: x (2048,128,32), clusters (32,128,32), out (2048,32)
#define N_TOTAL 2048
#define T_DIM   128
#define F_DIM   32
#define K_DIM   32
#define THREADS 512           // 16 warps = 4/SMSP
#define TCH     8             // t per chunk = one k8 tf32 MMA step
#define NCH     16
#define NROWS   16            // n rows per CTA
#define NBLOCKS (N_TOTAL / NROWS)   // 128

// ---- smem layout (bytes) ----
#define OFF_XNAT  0
#define XNAT_SZ   16384       // [16 n][8 t][8 fc] 16B cells, per slot (x2 slots)
#define OFF_CNAT  32768
#define CNAT_SZ   32768       // [32 k][8 t][8 fc] cells, per slot (x2 slots)
#define OFF_APL   98304       // A planes: 32 f x 132 words = 16896 B, x2 bufs
#define A_STRIDE  132
#define APL_SZ    16896
#define OFF_BPL   132096      // B planes: 32 f x 260 words = 33280 B, x2 bufs
#define B_STRIDE  260
#define BPL_SZ    33280
#define SMEM_TOTAL 198656     // ~194KB -> 1 CTA/SM
// epilogue overlays (main buffers dead)
#define OFF_X2RED 0           // [2 q][16 n][32 f] = 4KB
#define OFF_C2RED 4096        // [2 q][32 k][32 f] = 8KB
#define OFF_X2S   12288       // [16 n][32 f] = 2KB
#define OFF_C2S   14336       // [32 k][32 f] = 4KB
#define OFF_EPART 32768       // [16 w][16 n][32 k] = 32KB

__device__ __forceinline__ void cp_async16(uint32_t dst, const void* src) {
    asm volatile("cp.async.cg.shared.global [%0], [%1], 16;\n" :: "r"(dst), "l"(src));
}
__device__ __forceinline__ void cp_commit() {
    asm volatile("cp.async.commit_group;\n" ::: "memory");
}
__device__ __forceinline__ void cp_wait0() {
    asm volatile("cp.async.wait_group 0;\n" ::: "memory");
}
__device__ __forceinline__ void cp_wait1g() {
    asm volatile("cp.async.wait_group 1;\n" ::: "memory");
}
__device__ __forceinline__ float fsqrt_approx(float v) {
    float r; asm("sqrt.approx.f32 %0, %1;" : "=f"(r) : "f"(v)); return r;
}
__device__ __forceinline__ float frcp_approx(float v) {
    float r; asm("rcp.approx.f32 %0, %1;" : "=f"(r) : "f"(v)); return r;
}
__device__ __forceinline__ uint32_t cvt_tf32(float v) {
    uint32_t r; asm("cvt.rna.tf32.f32 %0, %1;" : "=r"(r) : "f"(v)); return r;
}
// m16n8k8 tf32 MMA — fragment layout validated in R13/R15
__device__ __forceinline__ void mma_tf32(float* d, const uint32_t* a, const uint32_t* b) {
    asm volatile("mma.sync.aligned.m16n8k8.row.col.f32.tf32.tf32.f32 "
        "{%0,%1,%2,%3}, {%4,%5,%6,%7}, {%8,%9}, {%0,%1,%2,%3};"
        : "+f"(d[0]), "+f"(d[1]), "+f"(d[2]), "+f"(d[3])
        : "r"(a[0]), "r"(a[1]), "r"(a[2]), "r"(a[3]), "r"(b[0]), "r"(b[1]));
}

extern "C" __global__ void __launch_bounds__(THREADS, 1)
ts_fused_kernel(const float* __restrict__ x, const float* __restrict__ clusters,
                float* __restrict__ out) {
    extern __shared__ char smem[];
    const uint32_t sb = (uint32_t)__cvta_generic_to_shared(smem);

    const int tid  = threadIdx.x;
    const int lane = tid & 31;
    const int w    = tid >> 5;           // 0..15
    const int g    = lane >> 2;          // MMA groupID
    const int t4   = lane & 3;           // MMA threadID-in-group
    const int n0   = blockIdx.x * NROWS;
    const int f0   = 2 * w;              // warp owns f-planes f0, f0+1

    // ---- cp.async addressing: natural cells, NO swizzle (reads are lane-
    //      consecutive across f so both sides are conflict-free) --------------
    const int t_ld  = (tid >> 3) & 7;
    const int fc_ld = tid & 7;
    const char* xsrc = (const char*)x
        + ((size_t)(n0 + (tid >> 6)) * T_DIM + t_ld) * 128 + (size_t)fc_ld * 16;
    const char* csrc = (const char*)clusters
        + ((size_t)(tid >> 6) * T_DIM + t_ld) * 128 + (size_t)fc_ld * 16;
    const uint32_t xdst = sb + OFF_XNAT + (uint32_t)tid * 16;
    const uint32_t cdst = sb + OFF_CNAT + (uint32_t)tid * 16;

    auto prefetch = [&](int ci) {
        const size_t tadv = (size_t)ci * TCH * 128;     // +1024B per chunk
        const uint32_t xo = (uint32_t)(ci & 1) * XNAT_SZ;
        const uint32_t co = (uint32_t)(ci & 1) * CNAT_SZ;
        #pragma unroll
        for (int r = 0; r < 2; r++)   // x: 1024 cells
            cp_async16(xdst + xo + (uint32_t)(r * 8192), xsrc + tadv + (size_t)r * 131072);
        #pragma unroll
        for (int r = 0; r < 4; r++)   // c: 2048 cells
            cp_async16(cdst + co + (uint32_t)(r * 8192), csrc + tadv + (size_t)r * 131072);
    };

    // ---- transpose task mapping ----------------------------------------------
    const int tf = tid & 31;             // f of transpose task (= lane!)
    const int tq = (tid >> 5) & 1;       // t-quad (t = 4q..4q+3)
    const int tn = tid >> 6;             // base row (+8r)

    float acc[2][4][4];
    #pragma unroll
    for (int fp = 0; fp < 2; fp++)
        #pragma unroll
        for (int nt = 0; nt < 4; nt++)
            #pragma unroll
            for (int e = 0; e < 4; e++) acc[fp][nt][e] = 0.f;
    float x2loc[2] = {0.f, 0.f};
    float c2loc[4] = {0.f, 0.f, 0.f, 0.f};

    // transpose chunk ci into plane buffer pb
    auto transpose = [&](int ci, int pb) {
        const float* xn = (const float*)(smem + OFF_XNAT + (ci & 1) * XNAT_SZ);
        const float* cn = (const float*)(smem + OFF_CNAT + (ci & 1) * CNAT_SZ);
        uint32_t* A = (uint32_t*)(smem + OFF_APL + pb * APL_SZ);
        uint32_t* B = (uint32_t*)(smem + OFF_BPL + pb * BPL_SZ);
        #pragma unroll
        for (int r = 0; r < 2; r++) {
            const int n = tn + 8 * r;
            uint32_t tv[4]; float s = x2loc[r];
            #pragma unroll
            for (int j = 0; j < 4; j++) {
                const int t = 4 * tq + j;
                float v = xn[(n * 8 + t) * 32 + tf];   // lane-consecutive
                tv[j] = cvt_tf32(v);
                s = fmaf(v, v, s);
            }
            x2loc[r] = s;
            *(uint4*)&A[tf * A_STRIDE + n * 8 + 4 * tq] =
                make_uint4(tv[0], tv[1], tv[2], tv[3]);
        }
        #pragma unroll
        for (int r = 0; r < 4; r++) {
            const int k = tn + 8 * r;
            uint32_t tv[4]; float s = c2loc[r];
            #pragma unroll
            for (int j = 0; j < 4; j++) {
                const int t = 4 * tq + j;
                float v = cn[(k * 8 + t) * 32 + tf];
                tv[j] = cvt_tf32(v);
                s = fmaf(v, v, s);
            }
            c2loc[r] = s;
            *(uint4*)&B[tf * B_STRIDE + k * 8 + 4 * tq] =
                make_uint4(tv[0], tv[1], tv[2], tv[3]);
        }
    };

    auto mma_chunk = [&](int pb) {
        #pragma unroll
        for (int fp = 0; fp < 2; fp++) {
            const uint32_t* Af = (const uint32_t*)(smem + OFF_APL + pb * APL_SZ)
                               + (f0 + fp) * A_STRIDE;
            const uint32_t* Bf = (const uint32_t*)(smem + OFF_BPL + pb * BPL_SZ)
                               + (f0 + fp) * B_STRIDE;
            uint32_t a[4];
            a[0] = Af[g * 8 + t4];        a[1] = Af[(g + 8) * 8 + t4];
            a[2] = Af[g * 8 + t4 + 4];    a[3] = Af[(g + 8) * 8 + t4 + 4];
            #pragma unroll
            for (int nt = 0; nt < 4; nt++) {
                uint32_t b[2];
                b[0] = Bf[(nt * 8 + g) * 8 + t4];
                b[1] = Bf[(nt * 8 + g) * 8 + t4 + 4];
                mma_tf32(acc[fp][nt], a, b);
            }
        }
    };

    // ---- pipeline: one barrier per chunk; MMA(ci) overlaps transpose(ci+1) ---
    prefetch(0); cp_commit();
    prefetch(1); cp_commit();
    cp_wait1g();                 // group 0 complete (own copies)
    __syncthreads();             // natural(0) visible to all
    transpose(0, 0);

    for (int ci = 0; ci < NCH; ci++) {
        cp_wait0();              // all pending groups done (natural ci+1 landed)
        __syncthreads();         // transpose(ci) + MMA(ci-1) complete everywhere
        if (ci + 2 < NCH) { prefetch(ci + 2); cp_commit(); }  // writes slot ci&1 (safe)
        if (ci + 1 < NCH) transpose(ci + 1, (ci + 1) & 1);
        mma_chunk(ci & 1);
    }
    __syncthreads();

    // ---- epilogue: reduce x2/c2 ----------------------------------------------
    float* x2red = (float*)(smem + OFF_X2RED);   // [q][n][f]
    float* c2red = (float*)(smem + OFF_C2RED);   // [q][k][f]
    float* x2s   = (float*)(smem + OFF_X2S);     // [n][f]
    float* c2s   = (float*)(smem + OFF_C2S);     // [k][f]
    float* epart = (float*)(smem + OFF_EPART);   // [w][n][k]

    #pragma unroll
    for (int r = 0; r < 2; r++)
        x2red[tq * 512 + (tn + 8 * r) * 32 + tf] = x2loc[r];
    #pragma unroll
    for (int r = 0; r < 4; r++)
        c2red[tq * 1024 + (tn + 8 * r) * 32 + tf] = c2loc[r];
    __syncthreads();

    x2s[tid] = x2red[tid] + x2red[tid + 512];
    #pragma unroll
    for (int e = 0; e < 2; e++) {
        int p = tid + 512 * e;
        c2s[p] = c2red[p] + c2red[p + 1024];
    }
    __syncthreads();

    // ---- sqrt + sum over this warp's 2 f's -> epart[w][n][k] ------------------
    #pragma unroll
    for (int nt = 0; nt < 4; nt++) {
        const int k0 = nt * 8 + 2 * t4, k1 = k0 + 1;
        float e00 = 0.f, e01 = 0.f, e10 = 0.f, e11 = 0.f;
        #pragma unroll
        for (int fp = 0; fp < 2; fp++) {
            const int f = f0 + fp;
            const float xa = x2s[g * 32 + f], xb = x2s[(g + 8) * 32 + f];
            const float ca = c2s[k0 * 32 + f], cb = c2s[k1 * 32 + f];
            e00 += fsqrt_approx(fmaxf(fmaf(-2.f, acc[fp][nt][0], xa + ca), 0.f));
            e01 += fsqrt_approx(fmaxf(fmaf(-2.f, acc[fp][nt][1], xa + cb), 0.f));
            e10 += fsqrt_approx(fmaxf(fmaf(-2.f, acc[fp][nt][2], xb + ca), 0.f));
            e11 += fsqrt_approx(fmaxf(fmaf(-2.f, acc[fp][nt][3], xb + cb), 0.f));
        }
        epart[w * 512 + g * 32 + k0]       = e00;
        epart[w * 512 + g * 32 + k1]       = e01;
        epart[w * 512 + (g + 8) * 32 + k0] = e10;
        epart[w * 512 + (g + 8) * 32 + k1] = e11;
    }
    __syncthreads();

    // ---- f-sum across warps + Student-t (warp w == n-row w) -------------------
    {
        float d = 0.f;
        #pragma unroll
        for (int ww = 0; ww < 16; ww++)
            d += epart[ww * 512 + tid];          // tid = n*32 + k
        float q = frcp_approx(fmaf(d, d, 1.0f)); // alpha = 1
        float s = q;
        #pragma unroll
        for (int off = 16; off > 0; off >>= 1)
            s += __shfl_xor_sync(0xffffffffu, s, off);
        out[(size_t)(n0 + w) * K_DIM + lane] = q * frcp_approx(s);
    }
}

extern "C" void kernel_launch(void* const* d_in, const int* in_sizes, int n_in,
                              void* d_out, int out_size) {
    const float* x        = (const float*)d_in[0];   // (2048, 128, 32)
    const float* clusters = (const float*)d_in[1];   // (32, 128, 32)
    float* out            = (float*)d_out;           // (2048, 32)
    (void)in_sizes; (void)n_in; (void)out_size;

    cudaFuncSetAttribute(ts_fused_kernel,
                         cudaFuncAttributeMaxDynamicSharedMemorySize, SMEM_TOTAL);
    ts_fused_kernel<<<NBLOCKS, THREADS, SMEM_TOTAL>>>(x, clusters, out);
}